// round 1
// baseline (speedup 1.0000x reference)
#include <cuda_runtime.h>
#include <cuda_bf16.h>
#include <math.h>

// Problem dims (gpt-small)
#define LAYERS 8
#define HEADS  8
#define CDIM   256
#define VDIM   128
#define TDIM   1024
#define BDIM   32
#define DDIM   32          // CDIM / HEADS
#define FFDIM  1024        // 4*CDIM
#define NTOK   (BDIM*TDIM) // 32768

// ---------------- scratch (device globals: allocation-free) ----------------
__device__ float g_x  [(size_t)NTOK*CDIM];   // residual stream
__device__ float g_h  [(size_t)NTOK*CDIM];   // layernorm output
__device__ float g_qkv[(size_t)NTOK*3*CDIM]; // qkv projection
__device__ float g_y  [(size_t)NTOK*CDIM];   // attention output
__device__ float g_ff [(size_t)NTOK*FFDIM];  // MLP hidden

// ---------------- embed: x = tok_emb[idx] + pos_emb ----------------
__global__ void embed_kernel(const int* __restrict__ idx,
                             const float* __restrict__ tok,
                             const float* __restrict__ pos,
                             float* __restrict__ x)
{
    int i = blockIdx.x * blockDim.x + threadIdx.x;
    if (i >= NTOK * CDIM) return;
    int c = i & (CDIM - 1);
    int row = i >> 8;            // token index b*T+t
    int t = row & (TDIM - 1);
    int tk = idx[row];
    x[i] = tok[tk * CDIM + c] + pos[t * CDIM + c];
}

// ---------------- layernorm: one block (256 thr) per token ----------------
__global__ void ln_kernel(const float* __restrict__ x,
                          const float* __restrict__ g,
                          const float* __restrict__ b,
                          float* __restrict__ out)
{
    int row = blockIdx.x;
    int c = threadIdx.x;
    float v = x[(size_t)row * CDIM + c];
    float s = v, s2 = v * v;
    #pragma unroll
    for (int o = 16; o; o >>= 1) {
        s  += __shfl_xor_sync(0xffffffffu, s,  o);
        s2 += __shfl_xor_sync(0xffffffffu, s2, o);
    }
    __shared__ float ss[8], ss2[8];
    __shared__ float m_sh, r_sh;
    int w = c >> 5, lane = c & 31;
    if (lane == 0) { ss[w] = s; ss2[w] = s2; }
    __syncthreads();
    if (c == 0) {
        float S = 0.f, S2 = 0.f;
        #pragma unroll
        for (int i = 0; i < 8; i++) { S += ss[i]; S2 += ss2[i]; }
        float m = S * (1.0f / CDIM);
        float var = S2 * (1.0f / CDIM) - m * m;
        m_sh = m;
        r_sh = rsqrtf(var + 1e-5f);
    }
    __syncthreads();
    out[(size_t)row * CDIM + c] = (v - m_sh) * r_sh * g[c] + b[c];
}

// ---------------- NewGELU (tanh approx, single MUFU exp) ----------------
__device__ __forceinline__ float gelu_f(float x)
{
    float a = 0.7978845608028654f * (x + 0.044715f * x * x * x);
    a = fminf(fmaxf(a, -15.f), 15.f);
    float e = __expf(2.0f * a);
    float t = (e - 1.0f) / (e + 1.0f);
    return 0.5f * x * (1.0f + t);
}

// ---------------- generic GEMM: C = A[M,K] @ B[K,N] (+bias)(gelu)(+res) ----
template<bool GELU, bool RES>
__global__ void gemm_k(const float* __restrict__ A, const float* __restrict__ B,
                       const float* __restrict__ bias, const float* __restrict__ res,
                       float* __restrict__ C, int M, int N, int K)
{
    __shared__ float As[16][68];   // transposed A tile, pad 68 keeps float4 align
    __shared__ float Bs[16][64];
    int tid = threadIdx.x;
    int tx = tid & 15, ty = tid >> 4;
    int row0 = blockIdx.y * 64, col0 = blockIdx.x * 64;
    float acc[4][4] = {};
    const float* Ab = A + (size_t)row0 * K;
    const float* Bb = B + col0;

    for (int k0 = 0; k0 < K; k0 += 16) {
        #pragma unroll
        for (int i = 0; i < 4; i++) {
            int li = tid + i * 256;
            int r = li >> 4, c = li & 15;      // A tile 64x16
            As[c][r] = Ab[(size_t)r * K + k0 + c];
            int r2 = li >> 6, c2 = li & 63;    // B tile 16x64
            Bs[r2][c2] = Bb[(size_t)(k0 + r2) * N + c2];
        }
        __syncthreads();
        #pragma unroll
        for (int k = 0; k < 16; k++) {
            float4 a4 = *reinterpret_cast<const float4*>(&As[k][ty * 4]);
            float4 b4 = *reinterpret_cast<const float4*>(&Bs[k][tx * 4]);
            float av[4] = {a4.x, a4.y, a4.z, a4.w};
            float bv[4] = {b4.x, b4.y, b4.z, b4.w};
            #pragma unroll
            for (int i = 0; i < 4; i++)
                #pragma unroll
                for (int j = 0; j < 4; j++)
                    acc[i][j] += av[i] * bv[j];
        }
        __syncthreads();
    }

    #pragma unroll
    for (int i = 0; i < 4; i++) {
        int r = row0 + ty * 4 + i;
        #pragma unroll
        for (int j = 0; j < 4; j++) {
            int c = col0 + tx * 4 + j;
            float v = acc[i][j];
            if (bias) v += bias[c];
            if (GELU) v = gelu_f(v);
            size_t o = (size_t)r * N + c;
            if (RES) v += res[o];
            C[o] = v;
        }
    }
}

// ---------------- flash attention: 64-query tile per (b,h) ----------------
// qkv layout: row = b*T+t, cols [0:256)=q, [256:512)=k, [512:768)=v; head h at h*32+d
__global__ void attn_kernel(const float* __restrict__ qkv, float* __restrict__ y)
{
    int qt = blockIdx.x;             // query tile 0..15
    int bh = blockIdx.y;             // 0..255
    int b = bh >> 3, h = bh & 7;
    int tid = threadIdx.x;
    int q  = tid >> 2;               // local query row 0..63
    int dg = tid & 3;                // d-group: owns d0..d0+7 of output
    int d0 = dg * 8;

    __shared__ float Qs[64][33], Ks[64][33], Vs[64][33], Ss[64][65];

    const size_t base = (size_t)b * TDIM * 768;
    int q0 = qt * 64;
    const float scale = 0.17677669529663687f;  // 1/sqrt(32)

    for (int li = tid; li < 64 * 32; li += 256) {
        int r = li >> 5, c = li & 31;
        Qs[r][c] = qkv[base + (size_t)(q0 + r) * 768 + h * 32 + c] * scale;
    }

    float m = -1e30f, l = 0.f, acc[8];
    #pragma unroll
    for (int j = 0; j < 8; j++) acc[j] = 0.f;

    for (int kt = 0; kt <= qt; kt++) {
        int k0 = kt * 64;
        __syncthreads();   // previous-tile consumers done (also covers Q load)
        for (int li = tid; li < 64 * 32; li += 256) {
            int r = li >> 5, c = li & 31;
            Ks[r][c] = qkv[base + (size_t)(k0 + r) * 768 + 256 + h * 32 + c];
            Vs[r][c] = qkv[base + (size_t)(k0 + r) * 768 + 512 + h * 32 + c];
        }
        __syncthreads();

        // scores for 16 owned keys
        float sv[16];
        #pragma unroll
        for (int i = 0; i < 16; i++) {
            int kk = dg * 16 + i;
            float s = 0.f;
            #pragma unroll
            for (int d = 0; d < 32; d++) s += Qs[q][d] * Ks[kk][d];
            if (kt == qt && kk > q) s = -1e30f;   // causal mask (k0 == q0 here)
            sv[i] = s;
        }
        // row max across the 4 lanes owning this q
        float mloc = sv[0];
        #pragma unroll
        for (int i = 1; i < 16; i++) mloc = fmaxf(mloc, sv[i]);
        mloc = fmaxf(mloc, __shfl_xor_sync(0xffffffffu, mloc, 1));
        mloc = fmaxf(mloc, __shfl_xor_sync(0xffffffffu, mloc, 2));
        float mnew  = fmaxf(m, mloc);
        float alpha = __expf(m - mnew);
        float lloc = 0.f;
        #pragma unroll
        for (int i = 0; i < 16; i++) {
            float p = __expf(sv[i] - mnew);
            lloc += p;
            Ss[q][dg * 16 + i] = p;
        }
        lloc += __shfl_xor_sync(0xffffffffu, lloc, 1);
        lloc += __shfl_xor_sync(0xffffffffu, lloc, 2);
        l = l * alpha + lloc;
        m = mnew;
        #pragma unroll
        for (int j = 0; j < 8; j++) acc[j] *= alpha;
        __syncwarp();  // Ss row q written only by this warp's 4-lane group
        for (int k = 0; k < 64; k++) {
            float p = Ss[q][k];
            #pragma unroll
            for (int j = 0; j < 8; j++) acc[j] += p * Vs[k][d0 + j];
        }
    }

    float inv = 1.0f / l;
    size_t orow = (size_t)(b * TDIM + q0 + q) * CDIM + h * 32 + d0;
    #pragma unroll
    for (int j = 0; j < 8; j++) y[orow + j] = acc[j] * inv;
}

// ---------------- host orchestration ----------------
static inline void run_gemm(const float* A, const float* B, const float* bias,
                            const float* res, float* C, int M, int N, int K,
                            bool gelu, bool resid)
{
    dim3 grid(N / 64, M / 64), block(256);
    if (gelu)        gemm_k<true,  false><<<grid, block>>>(A, B, bias, res, C, M, N, K);
    else if (resid)  gemm_k<false, true ><<<grid, block>>>(A, B, bias, res, C, M, N, K);
    else             gemm_k<false, false><<<grid, block>>>(A, B, bias, res, C, M, N, K);
}

extern "C" void kernel_launch(void* const* d_in, const int* in_sizes, int n_in,
                              void* d_out, int out_size)
{
    const int*   idx     = (const int*)  d_in[0];
    const float* tok_emb = (const float*)d_in[1];
    const float* pos_emb = (const float*)d_in[2];
    const float* ln1_g   = (const float*)d_in[3];
    const float* ln1_b   = (const float*)d_in[4];
    const float* wqkv    = (const float*)d_in[5];
    const float* bqkv    = (const float*)d_in[6];
    const float* wo      = (const float*)d_in[7];
    const float* bo      = (const float*)d_in[8];
    const float* ln2_g   = (const float*)d_in[9];
    const float* ln2_b   = (const float*)d_in[10];
    const float* wfc     = (const float*)d_in[11];
    const float* bfc     = (const float*)d_in[12];
    const float* wpr     = (const float*)d_in[13];
    const float* bpr     = (const float*)d_in[14];
    const float* lnf_g   = (const float*)d_in[15];
    const float* lnf_b   = (const float*)d_in[16];
    const float* w_lm    = (const float*)d_in[17];
    float* out = (float*)d_out;

    float *xp, *hp, *qkvp, *yp, *ffp;
    cudaGetSymbolAddress((void**)&xp,   g_x);
    cudaGetSymbolAddress((void**)&hp,   g_h);
    cudaGetSymbolAddress((void**)&qkvp, g_qkv);
    cudaGetSymbolAddress((void**)&yp,   g_y);
    cudaGetSymbolAddress((void**)&ffp,  g_ff);

    // embed
    {
        int n = NTOK * CDIM;
        embed_kernel<<<(n + 255) / 256, 256>>>(idx, tok_emb, pos_emb, xp);
    }

    for (int l = 0; l < LAYERS; l++) {
        const float* Wq = wqkv + (size_t)l * CDIM * 3 * CDIM;
        const float* bq = bqkv + (size_t)l * 3 * CDIM;
        const float* Wo = wo   + (size_t)l * CDIM * CDIM;
        const float* bo_= bo   + (size_t)l * CDIM;
        const float* Wf = wfc  + (size_t)l * CDIM * FFDIM;
        const float* bf = bfc  + (size_t)l * FFDIM;
        const float* Wp = wpr  + (size_t)l * FFDIM * CDIM;
        const float* bp = bpr  + (size_t)l * CDIM;

        // ln1
        ln_kernel<<<NTOK, 256>>>(xp, ln1_g + l * CDIM, ln1_b + l * CDIM, hp);
        // qkv projection
        run_gemm(hp, Wq, bq, nullptr, qkvp, NTOK, 3 * CDIM, CDIM, false, false);
        // attention
        {
            dim3 grid(TDIM / 64, BDIM * HEADS), block(256);
            attn_kernel<<<grid, block>>>(qkvp, yp);
        }
        // output projection + residual (in-place into x)
        run_gemm(yp, Wo, bo_, xp, xp, NTOK, CDIM, CDIM, false, true);
        // ln2
        ln_kernel<<<NTOK, 256>>>(xp, ln2_g + l * CDIM, ln2_b + l * CDIM, hp);
        // fc + gelu
        run_gemm(hp, Wf, bf, nullptr, ffp, NTOK, FFDIM, CDIM, true, false);
        // proj + residual
        run_gemm(ffp, Wp, bp, xp, xp, NTOK, CDIM, FFDIM, false, true);
    }

    // final LN + lm head (no bias)
    ln_kernel<<<NTOK, 256>>>(xp, lnf_g, lnf_b, hp);
    run_gemm(hp, w_lm, nullptr, nullptr, out, NTOK, VDIM, CDIM, false, false);
}

// round 3
// speedup vs baseline: 1.3645x; 1.3645x over previous
#include <cuda_runtime.h>
#include <cuda_bf16.h>
#include <math.h>
#include <stdint.h>

typedef __nv_bfloat16 bf16;

// ---------------- problem dims (gpt-small) ----------------
#define LAYERS 8
#define HEADS  8
#define CDIM   256
#define VDIM   128
#define TDIM   1024
#define BDIM   32
#define FFDIM  1024
#define NTOK   (BDIM*TDIM)   // 32768

// ---------------- scratch (device globals) ----------------
__device__ __align__(128) float g_x  [(size_t)NTOK*CDIM];     // residual stream
__device__ __align__(128) float g_qkv[(size_t)NTOK*3*CDIM];   // qkv (fp32)
__device__ __align__(128) bf16 g_hhi[(size_t)NTOK*CDIM], g_hlo[(size_t)NTOK*CDIM];
__device__ __align__(128) bf16 g_yhi[(size_t)NTOK*CDIM], g_ylo[(size_t)NTOK*CDIM];
__device__ __align__(128) bf16 g_fhi[(size_t)NTOK*FFDIM], g_flo[(size_t)NTOK*FFDIM];
// transposed + split weights: [N,K] (K-major rows)
__device__ __align__(128) bf16 g_wqh[(size_t)LAYERS*3*CDIM*CDIM], g_wql[(size_t)LAYERS*3*CDIM*CDIM];
__device__ __align__(128) bf16 g_woh[(size_t)LAYERS*CDIM*CDIM],   g_wol[(size_t)LAYERS*CDIM*CDIM];
__device__ __align__(128) bf16 g_wfh[(size_t)LAYERS*FFDIM*CDIM],  g_wfl[(size_t)LAYERS*FFDIM*CDIM];
__device__ __align__(128) bf16 g_wph[(size_t)LAYERS*CDIM*FFDIM],  g_wpl[(size_t)LAYERS*CDIM*FFDIM];
__device__ __align__(128) bf16 g_wlh[(size_t)VDIM*CDIM],          g_wll[(size_t)VDIM*CDIM];

// ---------------- PTX helpers (sm_80-era only: no 'a'-gated features) ----------------
__device__ __forceinline__ uint32_t smem_u32(const void* p) {
    uint32_t a;
    asm("{ .reg .u64 t; cvta.to.shared.u64 t, %1; cvt.u32.u64 %0, t; }" : "=r"(a) : "l"(p));
    return a;
}
__device__ __forceinline__ void cp16(uint32_t dst, const void* src) {
    asm volatile("cp.async.cg.shared.global [%0], [%1], 16;" :: "r"(dst), "l"(src));
}
#define CP_COMMIT() asm volatile("cp.async.commit_group;" ::: "memory")
#define CP_WAIT(n)  asm volatile("cp.async.wait_group %0;" :: "n"(n) : "memory")

__device__ __forceinline__ void ldmx4(uint32_t* r, uint32_t addr) {
    asm volatile("ldmatrix.sync.aligned.m8n8.x4.shared.b16 {%0,%1,%2,%3}, [%4];"
        : "=r"(r[0]), "=r"(r[1]), "=r"(r[2]), "=r"(r[3]) : "r"(addr));
}
__device__ __forceinline__ void mma16816(float* c, const uint32_t* a, const uint32_t* b) {
    asm volatile("mma.sync.aligned.m16n8k16.row.col.f32.bf16.bf16.f32 "
        "{%0,%1,%2,%3}, {%4,%5,%6,%7}, {%8,%9}, {%0,%1,%2,%3};"
        : "+f"(c[0]), "+f"(c[1]), "+f"(c[2]), "+f"(c[3])
        : "r"(a[0]), "r"(a[1]), "r"(a[2]), "r"(a[3]), "r"(b[0]), "r"(b[1]));
}

// ---------------- misc math ----------------
__device__ __forceinline__ float gelu_f(float x) {
    float a = 0.7978845608028654f * (x + 0.044715f * x * x * x);
    a = fminf(fmaxf(a, -15.f), 15.f);
    float e = __expf(2.0f * a);
    float t = (e - 1.0f) / (e + 1.0f);
    return 0.5f * x * (1.0f + t);
}
__device__ __forceinline__ void bf_split(float v, bf16& hi, bf16& lo) {
    hi = __float2bfloat16(v);
    lo = __float2bfloat16(v - __bfloat162float(hi));
}

// ---------------- embed ----------------
__global__ void embed_kernel(const int* __restrict__ idx,
                             const float* __restrict__ tok,
                             const float* __restrict__ pos,
                             float* __restrict__ x)
{
    int i = blockIdx.x * blockDim.x + threadIdx.x;
    if (i >= NTOK * CDIM) return;
    int c = i & (CDIM - 1);
    int row = i >> 8;
    int t = row & (TDIM - 1);
    x[i] = tok[idx[row] * CDIM + c] + pos[t * CDIM + c];
}

// ---------------- layernorm -> split bf16 ----------------
__global__ void ln_kernel(const float* __restrict__ x,
                          const float* __restrict__ g,
                          const float* __restrict__ b,
                          bf16* __restrict__ ohi, bf16* __restrict__ olo)
{
    int row = blockIdx.x;
    int c = threadIdx.x;
    float v = x[(size_t)row * CDIM + c];
    float s = v, s2 = v * v;
    #pragma unroll
    for (int o = 16; o; o >>= 1) {
        s  += __shfl_xor_sync(0xffffffffu, s,  o);
        s2 += __shfl_xor_sync(0xffffffffu, s2, o);
    }
    __shared__ float ss[8], ss2[8], m_sh, r_sh;
    int w = c >> 5, lane = c & 31;
    if (lane == 0) { ss[w] = s; ss2[w] = s2; }
    __syncthreads();
    if (c == 0) {
        float S = 0.f, S2 = 0.f;
        #pragma unroll
        for (int i = 0; i < 8; i++) { S += ss[i]; S2 += ss2[i]; }
        float m = S * (1.0f / CDIM);
        float var = S2 * (1.0f / CDIM) - m * m;
        m_sh = m; r_sh = rsqrtf(var + 1e-5f);
    }
    __syncthreads();
    float o = (v - m_sh) * r_sh * g[c] + b[c];
    size_t i = (size_t)row * CDIM + c;
    bf16 hi, lo; bf_split(o, hi, lo);
    ohi[i] = hi; olo[i] = lo;
}

// ---------------- weight transpose + split: W[K,N] -> T[N,K] hi/lo ----------------
__global__ void wsplit_kernel(const float* __restrict__ W,
                              bf16* __restrict__ Thi, bf16* __restrict__ Tlo,
                              int K, int N)
{
    __shared__ float t[32][33];
    int n0 = blockIdx.x << 5, k0 = blockIdx.y << 5;
    int tx = threadIdx.x, ty = threadIdx.y;  // (32,8)
    #pragma unroll
    for (int j = 0; j < 4; j++)
        t[ty + j * 8][tx] = W[(size_t)(k0 + ty + j * 8) * N + n0 + tx];
    __syncthreads();
    #pragma unroll
    for (int j = 0; j < 4; j++) {
        int nl = ty + j * 8;
        float v = t[tx][nl];
        size_t o = (size_t)(n0 + nl) * K + k0 + tx;
        bf16 hi, lo; bf_split(v, hi, lo);
        Thi[o] = hi; Tlo[o] = lo;
    }
}

// ---------------- HMMA split-bf16 GEMM ----------------
// D[M,N] = A[M,K] @ Bt[N,K]^T ; 3-product split, fp32 register accum.
// CTA tile 128x128, BK=32, 8 warps: warp tile 32 rows x 64 cols.
// SMEM stage: Ahi | Alo | Bhi | Blo, each 128 rows x 32 bf16, row stride 80 B.
#define GST   10240                 // bytes per matrix (128*80)
#define STAGE (4*GST)               // 40960
#define GSMEM (2*STAGE)             // 81920

__device__ __forceinline__ void g_fill(uint32_t st,
    const bf16* __restrict__ Ahi, const bf16* __restrict__ Alo,
    const bf16* __restrict__ Bhi, const bf16* __restrict__ Blo,
    int row0, int col0, int k0, int K, int tid)
{
    const bf16* base0 = Ahi + (size_t)row0 * K + k0;
    const bf16* base1 = Alo + (size_t)row0 * K + k0;
    const bf16* base2 = Bhi + (size_t)col0 * K + k0;
    const bf16* base3 = Blo + (size_t)col0 * K + k0;
    #pragma unroll
    for (int it = 0; it < 8; it++) {
        int i = tid + (it << 8);
        int mat = i >> 9, j = i & 511;
        int r = j >> 2, ch = j & 3;
        const bf16* src = (mat == 0) ? base0 : (mat == 1) ? base1 : (mat == 2) ? base2 : base3;
        cp16(st + mat * GST + r * 80 + ch * 16, src + (size_t)r * K + ch * 8);
    }
    CP_COMMIT();
}

template<bool GELU_, bool RES_, bool BF16OUT_, bool FP32OUT_>
__global__ void __launch_bounds__(256, 1) gemm_tc(
    const bf16* __restrict__ Ahi, const bf16* __restrict__ Alo,
    const bf16* __restrict__ Bhi, const bf16* __restrict__ Blo,
    const float* __restrict__ bias, const float* __restrict__ res,
    float* __restrict__ Cf, bf16* __restrict__ Chi, bf16* __restrict__ Clo,
    int M, int N, int K)
{
    extern __shared__ char smem[];
    const int tid  = threadIdx.x;
    const int wid  = tid >> 5;
    const int lane = tid & 31;
    const int warpM = wid & 3;          // 4 warp-rows of 32
    const int warpN = wid >> 2;         // 2 warp-cols of 64
    const int row0 = blockIdx.y << 7;
    const int col0 = blockIdx.x << 7;
    uint32_t sb = smem_u32(smem);

    float acc[2][8][4];
    #pragma unroll
    for (int mt = 0; mt < 2; mt++)
        #pragma unroll
        for (int nt = 0; nt < 8; nt++)
            #pragma unroll
            for (int j = 0; j < 4; j++) acc[mt][nt][j] = 0.f;

    const int nk = K >> 5;
    g_fill(sb, Ahi, Alo, Bhi, Blo, row0, col0, 0, K, tid);

    // precomputed ldmatrix lane addressing (byte offsets within a matrix region)
    const uint32_t aoff_base = (uint32_t)((warpM * 32 + (lane & 15)) * 80 + ((lane >> 4) & 1) * 16);
    const uint32_t boff_base = (uint32_t)((warpN * 64 + ((lane >> 4) & 1) * 8 + (lane & 7)) * 80
                                          + ((lane >> 3) & 1) * 16);

    for (int kt = 0; kt < nk; kt++) {
        uint32_t st = sb + (uint32_t)(kt & 1) * STAGE;
        if (kt + 1 < nk) {
            g_fill(sb + (uint32_t)((kt + 1) & 1) * STAGE, Ahi, Alo, Bhi, Blo,
                   row0, col0, (kt + 1) << 5, K, tid);
            CP_WAIT(1);
        } else {
            CP_WAIT(0);
        }
        __syncthreads();

        #pragma unroll
        for (int k16 = 0; k16 < 2; k16++) {
            uint32_t ka = st + aoff_base + k16 * 32;
            uint32_t kb = st + boff_base + k16 * 32;
            uint32_t ah[2][4], al[2][4], bh[4][4], bl[4][4];
            ldmx4(ah[0], ka);
            ldmx4(ah[1], ka + 16 * 80);
            ldmx4(al[0], ka + GST);
            ldmx4(al[1], ka + GST + 16 * 80);
            #pragma unroll
            for (int nt2 = 0; nt2 < 4; nt2++) {
                ldmx4(bh[nt2], kb + 2 * GST + nt2 * (16 * 80));
                ldmx4(bl[nt2], kb + 3 * GST + nt2 * (16 * 80));
            }
            #pragma unroll
            for (int mt = 0; mt < 2; mt++)
                #pragma unroll
                for (int nt = 0; nt < 8; nt++) {
                    const uint32_t* bhp = &bh[nt >> 1][(nt & 1) * 2];
                    const uint32_t* blp = &bl[nt >> 1][(nt & 1) * 2];
                    mma16816(acc[mt][nt], ah[mt], bhp);
                    mma16816(acc[mt][nt], ah[mt], blp);
                    mma16816(acc[mt][nt], al[mt], bhp);
                }
        }
        __syncthreads();
    }

    // ---- epilogue straight from registers ----
    const int g  = lane >> 2;
    const int tg = lane & 3;
    #pragma unroll
    for (int mt = 0; mt < 2; mt++) {
        #pragma unroll
        for (int half = 0; half < 2; half++) {
            int m = row0 + warpM * 32 + mt * 16 + g + half * 8;
            #pragma unroll
            for (int nt = 0; nt < 8; nt++) {
                int col = col0 + warpN * 64 + nt * 8 + tg * 2;
                float v0 = acc[mt][nt][half * 2 + 0];
                float v1 = acc[mt][nt][half * 2 + 1];
                if (bias) { v0 += bias[col]; v1 += bias[col + 1]; }
                if (GELU_) { v0 = gelu_f(v0); v1 = gelu_f(v1); }
                size_t o = (size_t)m * N + col;
                if (RES_) {
                    float2 r2 = *reinterpret_cast<const float2*>(&res[o]);
                    v0 += r2.x; v1 += r2.y;
                }
                if (FP32OUT_) {
                    *reinterpret_cast<float2*>(&Cf[o]) = make_float2(v0, v1);
                }
                if (BF16OUT_) {
                    bf16 h0, l0, h1, l1;
                    bf_split(v0, h0, l0); bf_split(v1, h1, l1);
                    __nv_bfloat162 hh; hh.x = h0; hh.y = h1;
                    __nv_bfloat162 ll; ll.x = l0; ll.y = l1;
                    *reinterpret_cast<__nv_bfloat162*>(&Chi[o]) = hh;
                    *reinterpret_cast<__nv_bfloat162*>(&Clo[o]) = ll;
                }
            }
        }
    }
}

// ---------------- flash attention (fp32), bf16 hi/lo output ----------------
__global__ void attn_kernel(const float* __restrict__ qkv,
                            bf16* __restrict__ yhi, bf16* __restrict__ ylo)
{
    int qt = blockIdx.x;
    int bh = blockIdx.y;
    int b = bh >> 3, h = bh & 7;
    int tid = threadIdx.x;
    int q  = tid >> 2;
    int dg = tid & 3;
    int d0 = dg * 8;

    __shared__ float Qs[64][33], Ks[64][33], Vs[64][33], Ss[64][65];

    const size_t base = (size_t)b * TDIM * 768;
    int q0 = qt * 64;
    const float scale = 0.17677669529663687f;

    for (int li = tid; li < 64 * 32; li += 256) {
        int r = li >> 5, c = li & 31;
        Qs[r][c] = qkv[base + (size_t)(q0 + r) * 768 + h * 32 + c] * scale;
    }

    float m = -1e30f, l = 0.f, acc[8];
    #pragma unroll
    for (int j = 0; j < 8; j++) acc[j] = 0.f;

    for (int kt = 0; kt <= qt; kt++) {
        int k0 = kt * 64;
        __syncthreads();
        for (int li = tid; li < 64 * 32; li += 256) {
            int r = li >> 5, c = li & 31;
            Ks[r][c] = qkv[base + (size_t)(k0 + r) * 768 + 256 + h * 32 + c];
            Vs[r][c] = qkv[base + (size_t)(k0 + r) * 768 + 512 + h * 32 + c];
        }
        __syncthreads();

        float sv[16];
        #pragma unroll
        for (int i = 0; i < 16; i++) {
            int kk = dg * 16 + i;
            float s = 0.f;
            #pragma unroll
            for (int d = 0; d < 32; d++) s += Qs[q][d] * Ks[kk][d];
            if (kt == qt && kk > q) s = -1e30f;
            sv[i] = s;
        }
        float mloc = sv[0];
        #pragma unroll
        for (int i = 1; i < 16; i++) mloc = fmaxf(mloc, sv[i]);
        mloc = fmaxf(mloc, __shfl_xor_sync(0xffffffffu, mloc, 1));
        mloc = fmaxf(mloc, __shfl_xor_sync(0xffffffffu, mloc, 2));
        float mnew  = fmaxf(m, mloc);
        float alpha = __expf(m - mnew);
        float lloc = 0.f;
        #pragma unroll
        for (int i = 0; i < 16; i++) {
            float p = __expf(sv[i] - mnew);
            lloc += p;
            Ss[q][dg * 16 + i] = p;
        }
        lloc += __shfl_xor_sync(0xffffffffu, lloc, 1);
        lloc += __shfl_xor_sync(0xffffffffu, lloc, 2);
        l = l * alpha + lloc;
        m = mnew;
        #pragma unroll
        for (int j = 0; j < 8; j++) acc[j] *= alpha;
        __syncwarp();
        for (int k = 0; k < 64; k++) {
            float p = Ss[q][k];
            #pragma unroll
            for (int j = 0; j < 8; j++) acc[j] += p * Vs[k][d0 + j];
        }
    }

    float inv = 1.0f / l;
    size_t orow = (size_t)(b * TDIM + q0 + q) * CDIM + h * 32 + d0;
    #pragma unroll
    for (int j = 0; j < 8; j++) {
        float v = acc[j] * inv;
        bf16 hi, lo; bf_split(v, hi, lo);
        yhi[orow + j] = hi; ylo[orow + j] = lo;
    }
}

// ---------------- host orchestration ----------------
extern "C" void kernel_launch(void* const* d_in, const int* in_sizes, int n_in,
                              void* d_out, int out_size)
{
    const int*   idx     = (const int*)  d_in[0];
    const float* tok_emb = (const float*)d_in[1];
    const float* pos_emb = (const float*)d_in[2];
    const float* ln1_g   = (const float*)d_in[3];
    const float* ln1_b   = (const float*)d_in[4];
    const float* wqkv    = (const float*)d_in[5];
    const float* bqkv    = (const float*)d_in[6];
    const float* wo      = (const float*)d_in[7];
    const float* bo      = (const float*)d_in[8];
    const float* ln2_g   = (const float*)d_in[9];
    const float* ln2_b   = (const float*)d_in[10];
    const float* wfc     = (const float*)d_in[11];
    const float* bfc     = (const float*)d_in[12];
    const float* wpr     = (const float*)d_in[13];
    const float* bpr     = (const float*)d_in[14];
    const float* lnf_g   = (const float*)d_in[15];
    const float* lnf_b   = (const float*)d_in[16];
    const float* w_lm    = (const float*)d_in[17];
    float* out = (float*)d_out;

    float *xp, *qkvp;
    bf16 *hhi, *hlo, *yhi, *ylo, *fhi, *flo;
    bf16 *wqh, *wql, *woh, *wol, *wfh, *wfl, *wph, *wpl, *wlh, *wll;
    cudaGetSymbolAddress((void**)&xp,   g_x);
    cudaGetSymbolAddress((void**)&qkvp, g_qkv);
    cudaGetSymbolAddress((void**)&hhi,  g_hhi);  cudaGetSymbolAddress((void**)&hlo, g_hlo);
    cudaGetSymbolAddress((void**)&yhi,  g_yhi);  cudaGetSymbolAddress((void**)&ylo, g_ylo);
    cudaGetSymbolAddress((void**)&fhi,  g_fhi);  cudaGetSymbolAddress((void**)&flo, g_flo);
    cudaGetSymbolAddress((void**)&wqh,  g_wqh);  cudaGetSymbolAddress((void**)&wql, g_wql);
    cudaGetSymbolAddress((void**)&woh,  g_woh);  cudaGetSymbolAddress((void**)&wol, g_wol);
    cudaGetSymbolAddress((void**)&wfh,  g_wfh);  cudaGetSymbolAddress((void**)&wfl, g_wfl);
    cudaGetSymbolAddress((void**)&wph,  g_wph);  cudaGetSymbolAddress((void**)&wpl, g_wpl);
    cudaGetSymbolAddress((void**)&wlh,  g_wlh);  cudaGetSymbolAddress((void**)&wll, g_wll);

    cudaFuncSetAttribute(gemm_tc<false, false, false, true>,
                         cudaFuncAttributeMaxDynamicSharedMemorySize, GSMEM);
    cudaFuncSetAttribute(gemm_tc<false, true, false, true>,
                         cudaFuncAttributeMaxDynamicSharedMemorySize, GSMEM);
    cudaFuncSetAttribute(gemm_tc<true, false, true, false>,
                         cudaFuncAttributeMaxDynamicSharedMemorySize, GSMEM);

    // ---- weight prep (transpose + bf16 split) ----
    dim3 wb(32, 8);
    for (int l = 0; l < LAYERS; l++) {
        wsplit_kernel<<<dim3(24, 8), wb>>>(wqkv + (size_t)l * CDIM * 3 * CDIM,
                                           wqh + (size_t)l * 3 * CDIM * CDIM,
                                           wql + (size_t)l * 3 * CDIM * CDIM, CDIM, 3 * CDIM);
        wsplit_kernel<<<dim3(8, 8),  wb>>>(wo + (size_t)l * CDIM * CDIM,
                                           woh + (size_t)l * CDIM * CDIM,
                                           wol + (size_t)l * CDIM * CDIM, CDIM, CDIM);
        wsplit_kernel<<<dim3(32, 8), wb>>>(wfc + (size_t)l * CDIM * FFDIM,
                                           wfh + (size_t)l * FFDIM * CDIM,
                                           wfl + (size_t)l * FFDIM * CDIM, CDIM, FFDIM);
        wsplit_kernel<<<dim3(8, 32), wb>>>(wpr + (size_t)l * FFDIM * CDIM,
                                           wph + (size_t)l * CDIM * FFDIM,
                                           wpl + (size_t)l * CDIM * FFDIM, FFDIM, CDIM);
    }
    wsplit_kernel<<<dim3(4, 8), wb>>>(w_lm, wlh, wll, CDIM, VDIM);

    embed_kernel<<<(NTOK * CDIM + 255) / 256, 256>>>(idx, tok_emb, pos_emb, xp);

    for (int l = 0; l < LAYERS; l++) {
        const float* bq  = bqkv + (size_t)l * 3 * CDIM;
        const float* bo_ = bo   + (size_t)l * CDIM;
        const float* bf  = bfc  + (size_t)l * FFDIM;
        const float* bp  = bpr  + (size_t)l * CDIM;
        bf16* Wqh = wqh + (size_t)l * 3 * CDIM * CDIM;  bf16* Wql = wql + (size_t)l * 3 * CDIM * CDIM;
        bf16* Woh = woh + (size_t)l * CDIM * CDIM;      bf16* Wol = wol + (size_t)l * CDIM * CDIM;
        bf16* Wfh = wfh + (size_t)l * FFDIM * CDIM;     bf16* Wfl = wfl + (size_t)l * FFDIM * CDIM;
        bf16* Wph = wph + (size_t)l * CDIM * FFDIM;     bf16* Wpl = wpl + (size_t)l * CDIM * FFDIM;

        ln_kernel<<<NTOK, 256>>>(xp, ln1_g + l * CDIM, ln1_b + l * CDIM, hhi, hlo);

        gemm_tc<false, false, false, true><<<dim3(6, NTOK / 128), 256, GSMEM>>>(
            hhi, hlo, Wqh, Wql, bq, nullptr, qkvp, nullptr, nullptr, NTOK, 3 * CDIM, CDIM);

        attn_kernel<<<dim3(TDIM / 64, BDIM * HEADS), 256>>>(qkvp, yhi, ylo);

        gemm_tc<false, true, false, true><<<dim3(2, NTOK / 128), 256, GSMEM>>>(
            yhi, ylo, Woh, Wol, bo_, xp, xp, nullptr, nullptr, NTOK, CDIM, CDIM);

        ln_kernel<<<NTOK, 256>>>(xp, ln2_g + l * CDIM, ln2_b + l * CDIM, hhi, hlo);

        gemm_tc<true, false, true, false><<<dim3(8, NTOK / 128), 256, GSMEM>>>(
            hhi, hlo, Wfh, Wfl, bf, nullptr, nullptr, fhi, flo, NTOK, FFDIM, CDIM);

        gemm_tc<false, true, false, true><<<dim3(2, NTOK / 128), 256, GSMEM>>>(
            fhi, flo, Wph, Wpl, bp, xp, xp, nullptr, nullptr, NTOK, CDIM, FFDIM);
    }

    ln_kernel<<<NTOK, 256>>>(xp, lnf_g, lnf_b, hhi, hlo);
    gemm_tc<false, false, false, true><<<dim3(1, NTOK / 128), 256, GSMEM>>>(
        hhi, hlo, wlh, wll, nullptr, nullptr, out, nullptr, nullptr, NTOK, VDIM, CDIM);
}